// round 5
// baseline (speedup 1.0000x reference)
#include <cuda_runtime.h>

// Attention: B=2, H=16, S=2048, D=64 (fp32), mask int32 [B,1,S,S]
// Outputs concatenated in d_out: out [B,H,S,D] then p_attn [B,H,S,S].
//
// Per (b,h, qtile=128) block, 256 threads:
//   Pass 1: 128x128 QK^T tiles (8x8 microtile) -> raw masked scores to p_attn,
//           flash-style online (m, l) in registers; per-row m, 1/l parked in smem.
//   Pass 2: cooperative re-read of scores, finalize p = exp(s-m)/l (overwrite
//           p_attn), stage p in natural [q][k] smem, out += p @ V (4x8 microtile).

#define S_LEN 2048
#define D_HEAD 64
#define TQ 128

__global__ __launch_bounds__(256, 2)
void attn_kernel(const float* __restrict__ Q,
                 const float* __restrict__ K,
                 const float* __restrict__ V,
                 const int*   __restrict__ M,
                 float* __restrict__ Out,
                 float* __restrict__ P)
{
    extern __shared__ float sm[];
    float* sMx = sm;         // [128] row max
    float* sLi = sm + 128;   // [128] 1/l
    float* s0  = sm + 256;
    // pass1 union: sQt [64][132], sKt [64][132]
    // pass2 union: sP  [128][132], sV [128][68]
    float* sQt = s0;
    float* sKt = s0 + 64 * 132;
    float* sP  = s0;
    float* sV  = s0 + 128 * 132;

    const int tid = threadIdx.x;
    const int tx  = tid & 15;     // pass1: k-col group
    const int ty  = tid >> 4;     // pass1: q-row group
    const int bh  = blockIdx.y;
    const int q0  = blockIdx.x * TQ;

    const float* qp = Q + ((size_t)bh * S_LEN + q0) * D_HEAD;
    const float* kp = K + (size_t)bh * S_LEN * D_HEAD;
    const float* vp = V + (size_t)bh * S_LEN * D_HEAD;
    const int*   mp = M + (size_t)(bh >> 4) * S_LEN * S_LEN + (size_t)q0 * S_LEN;
    float* pp = P   + ((size_t)bh * S_LEN + q0) * S_LEN;
    float* op = Out + ((size_t)bh * S_LEN + q0) * D_HEAD;

    // ---- load Q tile (128x64) transposed into sQt[d][q] ----
    {
        const int c = tx * 4;
        #pragma unroll
        for (int it = 0; it < 8; ++it) {
            const int row = ty + it * 16;
            float4 v = *(const float4*)(qp + row * D_HEAD + c);
            sQt[(c + 0) * 132 + row] = v.x;
            sQt[(c + 1) * 132 + row] = v.y;
            sQt[(c + 2) * 132 + row] = v.z;
            sQt[(c + 3) * 132 + row] = v.w;
        }
    }

    float m_run[8], l_run[8];
    #pragma unroll
    for (int i = 0; i < 8; ++i) { m_run[i] = -3.0e38f; l_run[i] = 0.0f; }

    // ================= Pass 1: scores + online stats =================
    for (int kt = 0; kt < S_LEN; kt += 128) {
        __syncthreads();
        // load K tile (128x64) transposed into sKt[d][k]
        {
            const int c = tx * 4;
            #pragma unroll
            for (int it = 0; it < 8; ++it) {
                const int row = ty + it * 16;
                float4 v = *(const float4*)(kp + (size_t)(kt + row) * D_HEAD + c);
                sKt[(c + 0) * 132 + row] = v.x;
                sKt[(c + 1) * 132 + row] = v.y;
                sKt[(c + 2) * 132 + row] = v.z;
                sKt[(c + 3) * 132 + row] = v.w;
            }
        }
        __syncthreads();

        float acc[8][8];
        #pragma unroll
        for (int i = 0; i < 8; ++i)
            #pragma unroll
            for (int j = 0; j < 8; ++j) acc[i][j] = 0.0f;

        #pragma unroll 8
        for (int d = 0; d < 64; ++d) {
            float4 a0 = *(const float4*)(sQt + d * 132 + 8 * ty);
            float4 a1 = *(const float4*)(sQt + d * 132 + 8 * ty + 4);
            float4 b0 = *(const float4*)(sKt + d * 132 + 4 * tx);
            float4 b1 = *(const float4*)(sKt + d * 132 + 64 + 4 * tx);
            const float av[8] = {a0.x, a0.y, a0.z, a0.w, a1.x, a1.y, a1.z, a1.w};
            const float bv[8] = {b0.x, b0.y, b0.z, b0.w, b1.x, b1.y, b1.z, b1.w};
            #pragma unroll
            for (int i = 0; i < 8; ++i)
                #pragma unroll
                for (int j = 0; j < 8; ++j)
                    acc[i][j] += av[i] * bv[j];
        }

        #pragma unroll
        for (int i = 0; i < 8; ++i) {
            const int qr = 8 * ty + i;
            const int4 mv0 = *(const int4*)(mp + (size_t)qr * S_LEN + kt + 4 * tx);
            const int4 mv1 = *(const int4*)(mp + (size_t)qr * S_LEN + kt + 64 + 4 * tx);
            float s[8];
            s[0] = mv0.x ? acc[i][0] * 0.125f : -1.0e9f;
            s[1] = mv0.y ? acc[i][1] * 0.125f : -1.0e9f;
            s[2] = mv0.z ? acc[i][2] * 0.125f : -1.0e9f;
            s[3] = mv0.w ? acc[i][3] * 0.125f : -1.0e9f;
            s[4] = mv1.x ? acc[i][4] * 0.125f : -1.0e9f;
            s[5] = mv1.y ? acc[i][5] * 0.125f : -1.0e9f;
            s[6] = mv1.z ? acc[i][6] * 0.125f : -1.0e9f;
            s[7] = mv1.w ? acc[i][7] * 0.125f : -1.0e9f;
            *(float4*)(pp + (size_t)qr * S_LEN + kt + 4 * tx) =
                make_float4(s[0], s[1], s[2], s[3]);
            *(float4*)(pp + (size_t)qr * S_LEN + kt + 64 + 4 * tx) =
                make_float4(s[4], s[5], s[6], s[7]);

            float tmax = fmaxf(fmaxf(fmaxf(s[0], s[1]), fmaxf(s[2], s[3])),
                               fmaxf(fmaxf(s[4], s[5]), fmaxf(s[6], s[7])));
            #pragma unroll
            for (int off = 8; off > 0; off >>= 1)
                tmax = fmaxf(tmax, __shfl_xor_sync(0xffffffffu, tmax, off, 16));
            const float m_new = fmaxf(m_run[i], tmax);
            float es = 0.0f;
            #pragma unroll
            for (int u = 0; u < 8; ++u) es += __expf(s[u] - m_new);
            #pragma unroll
            for (int off = 8; off > 0; off >>= 1)
                es += __shfl_xor_sync(0xffffffffu, es, off, 16);
            l_run[i] = l_run[i] * __expf(m_run[i] - m_new) + es;
            m_run[i] = m_new;
        }
    }

    // park per-row stats for pass-2 (different thread mapping)
    if (tx == 0) {
        #pragma unroll
        for (int i = 0; i < 8; ++i) {
            sMx[8 * ty + i] = m_run[i];
            sLi[8 * ty + i] = 1.0f / l_run[i];
        }
    }
    __syncthreads();

    // ================= Pass 2: finalize p, out += p @ V =================
    const int ty2 = tid >> 3;   // q-row group (0..31) -> rows 4*ty2+i
    const int tx2 = tid & 7;    // d-col group (0..7)  -> cols 8*tx2+j

    float m2[4], il2[4];
    #pragma unroll
    for (int i = 0; i < 4; ++i) {
        m2[i]  = sMx[4 * ty2 + i];
        il2[i] = sLi[4 * ty2 + i];
    }

    float acc2[4][8];
    #pragma unroll
    for (int i = 0; i < 4; ++i)
        #pragma unroll
        for (int j = 0; j < 8; ++j) acc2[i][j] = 0.0f;

    for (int kt = 0; kt < S_LEN; kt += 128) {
        __syncthreads();
        // V tile [128k][64d] -> sV[k][d]
        #pragma unroll
        for (int it = 0; it < 8; ++it) {
            const int idx = tid + it * 256;
            const int r = idx >> 4;
            const int c = (idx & 15) * 4;
            float4 v = *(const float4*)(vp + (size_t)(kt + r) * D_HEAD + c);
            *(float4*)(sV + r * 68 + c) = v;
        }
        // scores: coalesced re-read, finalize p, write back + stage in sP[q][k]
        #pragma unroll
        for (int it = 0; it < 16; ++it) {
            const int idx = tid + it * 256;
            const int r = idx >> 5;
            const int c = (idx & 31) * 4;
            float4 s = *(const float4*)(pp + (size_t)r * S_LEN + kt + c);
            const float mr = sMx[r], il = sLi[r];
            float4 p;
            p.x = __expf(s.x - mr) * il;
            p.y = __expf(s.y - mr) * il;
            p.z = __expf(s.z - mr) * il;
            p.w = __expf(s.w - mr) * il;
            *(float4*)(pp + (size_t)r * S_LEN + kt + c) = p;
            *(float4*)(sP + r * 132 + c) = p;
        }
        __syncthreads();

        #pragma unroll 2
        for (int kk = 0; kk < 128; kk += 4) {
            float4 a4[4];
            #pragma unroll
            for (int i = 0; i < 4; ++i)
                a4[i] = *(const float4*)(sP + (4 * ty2 + i) * 132 + kk);
            #pragma unroll
            for (int u = 0; u < 4; ++u) {
                float4 b0 = *(const float4*)(sV + (kk + u) * 68 + 8 * tx2);
                float4 b1 = *(const float4*)(sV + (kk + u) * 68 + 8 * tx2 + 4);
                const float bv[8] = {b0.x, b0.y, b0.z, b0.w, b1.x, b1.y, b1.z, b1.w};
                #pragma unroll
                for (int i = 0; i < 4; ++i) {
                    const float av = ((const float*)&a4[i])[u];
                    #pragma unroll
                    for (int j = 0; j < 8; ++j)
                        acc2[i][j] += av * bv[j];
                }
            }
        }
    }

    #pragma unroll
    for (int i = 0; i < 4; ++i) {
        *(float4*)(op + (size_t)(4 * ty2 + i) * D_HEAD + 8 * tx2) =
            make_float4(acc2[i][0], acc2[i][1], acc2[i][2], acc2[i][3]);
        *(float4*)(op + (size_t)(4 * ty2 + i) * D_HEAD + 8 * tx2 + 4) =
            make_float4(acc2[i][4], acc2[i][5], acc2[i][6], acc2[i][7]);
    }
}

extern "C" void kernel_launch(void* const* d_in, const int* in_sizes, int n_in,
                              void* d_out, int out_size)
{
    const float* q = (const float*)d_in[0];
    const float* k = (const float*)d_in[1];
    const float* v = (const float*)d_in[2];
    const int*   m = (const int*)d_in[3];
    float* out = (float*)d_out;
    float* p   = out + (size_t)2 * 16 * 2048 * 64;

    const int smem_bytes = (256 + 128 * 132 + 128 * 68) * 4;  // 103424
    cudaFuncSetAttribute(attn_kernel,
                         cudaFuncAttributeMaxDynamicSharedMemorySize, smem_bytes);
    dim3 grid(S_LEN / TQ, 2 * 16);
    attn_kernel<<<grid, 256, smem_bytes>>>(q, k, v, m, out, p);
}